// round 3
// baseline (speedup 1.0000x reference)
#include <cuda_runtime.h>
#include <cuda_bf16.h>

// CTC forward loss (log-semiring DP), shapes fixed by the problem instance:
//   log_probs [B=32, T=2000, V=1024] f32, targets [B, S=128] i32,
//   input_lengths [B] i32, target_lengths [B] i32  ->  scalar f32 (sum of NLL)
//
// One CTA per batch; thread l owns lattice state l (L = 2S+1 = 257; thread 255
// also owns state 256). Per-timestep neighbor exchange through double-buffered
// shared memory with NEG sentinels; one __syncthreads per step. LSE computed in
// log2 domain with MUFU ex2/lg2. Emissions register-prefetched PD steps ahead.

#define NEGF (-1e30f)
#define LOG2E_F 1.4426950408889634f
#define LN2_F   0.6931471805599453f

static constexpr int B_ = 32;
static constexpr int T_ = 2000;
static constexpr int V_ = 1024;
static constexpr int S_ = 128;
static constexpr int L_ = 2 * S_ + 1;   // 257
static constexpr int NTHREADS = 256;
static constexpr int PD = 10;           // emission prefetch depth (timesteps)

__device__ __forceinline__ float ex2f_(float x) {
    float y; asm("ex2.approx.f32 %0, %1;" : "=f"(y) : "f"(x)); return y;
}
__device__ __forceinline__ float lg2f_(float x) {
    float y; asm("lg2.approx.f32 %0, %1;" : "=f"(y) : "f"(x)); return y;
}

__global__ void ctc_zero_kernel(float* out, int n) {
    int i = blockIdx.x * blockDim.x + threadIdx.x;
    if (i < n) out[i] = 0.0f;
}

__global__ __launch_bounds__(NTHREADS, 1)
void ctc_forward_kernel(const float* __restrict__ logp,
                        const int* __restrict__ targets,
                        const int* __restrict__ in_len,
                        const int* __restrict__ tg_len,
                        float* __restrict__ out)
{
    // sh[buf][l + 2] holds alpha[l]; sh[buf][0..1] are NEG sentinels (l = -2, -1).
    __shared__ float sh[2][L_ + 4];

    const int b = blockIdx.x;
    const int l = threadIdx.x;                 // state index 0..255
    const bool dual = (l == NTHREADS - 1);     // thread 255 also owns state 256

    // Extended label for this state and skip-transition predicate.
    int lab;
    bool skipok;
    if (l & 1) {
        const int s = l >> 1;
        lab = targets[b * S_ + s];
        skipok = (s == 0) ? true : (lab != targets[b * S_ + s - 1]);
    } else {
        lab = 0;          // blank
        skipok = false;
    }

    const float* ptr = logp + (size_t)b * T_ * V_ + lab;
    const int Tlim = min(in_len[b], T_);

    // t = 0 initialization (log2 domain).
    float alpha  = (l <= 1) ? ptr[0] * LOG2E_F : NEGF;
    float alpha2 = NEGF;   // state 256 (dual thread only)

    if (l < 2) { sh[0][l] = NEGF; sh[1][l] = NEGF; }
    sh[0][l + 2] = alpha;

    // Prime the emission prefetch pipeline for t = 1..PD.
    float pref[PD];
#pragma unroll
    for (int j = 0; j < PD; j++) {
        const int t = 1 + j;
        pref[j] = (t < Tlim) ? ptr[(size_t)t * V_] : 0.0f;
    }

    int p = 0;
    for (int t0 = 1; t0 < Tlim; t0 += PD) {
#pragma unroll
        for (int j = 0; j < PD; j++) {
            const int t = t0 + j;
            if (t >= Tlim) break;                       // uniform across CTA

            const float e = pref[j] * LOG2E_F;
            const int tn = t + PD;
            pref[j] = (tn < Tlim) ? ptr[(size_t)tn * V_] : 0.0f;

            // Blank emission for the dual state: lane 0 of each warp holds an
            // even (blank) state, so its e is log_probs[b, t, 0] * log2(e).
            const float eb = __shfl_sync(0xffffffffu, e, 0);

            __syncthreads();                            // sh[p] fully published

            const float a1 = alpha;
            const float a2 = sh[p][l + 1];              // alpha[l-1]
            const float a3 = skipok ? sh[p][l] : NEGF;  // alpha[l-2]

            const float m  = fmaxf(a1, fmaxf(a2, a3));
            const float s  = ex2f_(a1 - m) + ex2f_(a2 - m) + ex2f_(a3 - m);
            const float na = m + lg2f_(s) + e;

            if (dual) {                                 // state 256: 2-way LSE
                const float mb = fmaxf(alpha2, a1);
                const float sb = ex2f_(alpha2 - mb) + ex2f_(a1 - mb);
                alpha2 = mb + lg2f_(sb) + eb;
            }

            alpha = na;
            sh[p ^ 1][l + 2] = na;
            p ^= 1;
        }
    }

    // Final readout. After the loop, sh[p] holds the final alphas for l<=255.
    if (dual) sh[p][L_ + 1] = alpha2;                   // state 256 at index 258
    __syncthreads();

    if (l == 0) {
        const int tl = min(tg_len[b], S_);
        const int i1 = 2 * tl;
        const int i2 = max(i1 - 1, 0);
        const float x = sh[p][i1 + 2];
        const float y = sh[p][i2 + 2];
        const float m = fmaxf(x, y);
        const float ll2 = m + lg2f_(ex2f_(x - m) + ex2f_(y - m));
        atomicAdd(out, -ll2 * LN2_F);                   // back to natural log
    }
}

extern "C" void kernel_launch(void* const* d_in, const int* in_sizes, int n_in,
                              void* d_out, int out_size)
{
    const float* logp    = (const float*)d_in[0];
    const int*   targets = (const int*)d_in[1];
    const int*   in_len  = (const int*)d_in[2];
    const int*   tg_len  = (const int*)d_in[3];
    float*       out     = (float*)d_out;

    ctc_zero_kernel<<<(out_size + 255) / 256, 256>>>(out, out_size);

    const int B = in_sizes[2];   // number of utterances (32)
    ctc_forward_kernel<<<B, NTHREADS>>>(logp, targets, in_len, tg_len, out);
}

// round 5
// speedup vs baseline: 1.4134x; 1.4134x over previous
#include <cuda_runtime.h>
#include <cuda_bf16.h>

// CTC forward loss in linear-probability domain with PER-LANE block floating
// point. Shapes fixed: log_probs [B=32,T=2000,V=1024] f32, targets [B,128] i32,
// lengths [B] i32 -> scalar f32 (sum of NLL).
//
//  1) zero_k   : clear output
//  2) gather_k : compact logp[b,t,label_s] -> g_compact[b,t,0..128] once at
//                full-chip parallelism (labels are time-invariant; 34MB fits L2)
//  3) ctc_dp   : one warp per batch, 257 states in registers (8/lane, lane 31
//                holds a 9th). Jacobi step a'[l] = (a[l]+a[l-1]+skip*a[l-2])*p.
//                Only a[8k-1] crosses lanes -> ONE value shfl per step.
//                Each lane keeps its own power-of-two scale sacc_k (states
//                renormed to lane-local max every 8 steps); the shfl'd value is
//                rescaled by cross = 2^(sacc_k - sacc_{k-1}). This gives an
//                effectively unbounded global dynamic range (the global spread
//                across 257 states reaches ~300 nats, far beyond fp32).

#define L2E_F 1.4426950408889634f
#define LN2_F 0.6931471805599453f

static constexpr int Bc = 32;
static constexpr int Tc = 2000;
static constexpr int Vc = 1024;
static constexpr int Sc = 128;
static constexpr int CW = 132;            // compact row stride in floats (16B-mult)

__device__ float g_compact[(size_t)Bc * Tc * CW];

__device__ __forceinline__ float ex2f(float x) {
    float y; asm("ex2.approx.f32 %0, %1;" : "=f"(y) : "f"(x)); return y;
}
__device__ __forceinline__ float lg2f(float x) {
    float y; asm("lg2.approx.f32 %0, %1;" : "=f"(y) : "f"(x)); return y;
}
__device__ __forceinline__ float pow2i(int s) {      // s in [-126,127]
    return __uint_as_float((unsigned)(127 + s) << 23);
}

__global__ void zero_k(float* o, int n) {
    int i = blockIdx.x * blockDim.x + threadIdx.x;
    if (i < n) o[i] = 0.0f;
}

// grid ((Tc+3)/4, B), block 512: 4 time-rows per block, 128 label-threads each.
__global__ void gather_k(const float* __restrict__ logp, const int* __restrict__ tg)
{
    const int b = blockIdx.y;
    const int j = threadIdx.x & 127;
    const int t = blockIdx.x * 4 + (threadIdx.x >> 7);
    if (t >= Tc) return;
    const size_t ri = ((size_t)b * Tc + t) * Vc;
    const size_t ro = ((size_t)b * Tc + t) * CW;
    const int lab = tg[b * Sc + j];
    g_compact[ro + j] = logp[ri + lab];
    if (j == 0) g_compact[ro + 128] = logp[ri];       // blank = vocab 0
}

__global__ __launch_bounds__(32, 1)
void ctc_dp(const int* __restrict__ tg, const int* __restrict__ il,
            const int* __restrict__ tl, float* __restrict__ out)
{
    const int b = blockIdx.x;
    const int k = threadIdx.x;                 // lane: states 8k..8k+7 (+256 on lane 31)
    const float* cmp = g_compact + (size_t)b * Tc * CW;

    // Skip-transition coefficients: label s vs s-1, s = 4k..4k+3.
    const int l0 = tg[b * Sc + 4 * k + 0];
    const int l1 = tg[b * Sc + 4 * k + 1];
    const int l2 = tg[b * Sc + 4 * k + 2];
    const int l3 = tg[b * Sc + 4 * k + 3];
    const int lm = (k == 0) ? -1 : tg[b * Sc + 4 * k - 1];
    const float c1 = (l0 != lm) ? 1.f : 0.f;
    const float c3 = (l1 != l0) ? 1.f : 0.f;
    const float c5 = (l2 != l1) ? 1.f : 0.f;
    const float c7 = (l3 != l2) ? 1.f : 0.f;

    const int Tl = min(il[b], Tc);

    // States, stored = true * 2^sacc (per-lane scale). Init t=0 at 2^64.
    float a0=0.f,a1=0.f,a2=0.f,a3=0.f,a4=0.f,a5=0.f,a6=0.f,a7=0.f,a8=0.f;
    if (k == 0) {
        a0 = ex2f(cmp[128] * L2E_F + 64.f);    // state 0: blank
        a1 = ex2f(cmp[0]   * L2E_F + 64.f);    // state 1: label s=0
    }
    int sacc = 64;
    float cross = 1.0f;                        // 2^(sacc_k - sacc_{k-1})

    // Emission prefetch ring, 8 steps deep (compact buffer is L2-resident).
    float4 pf[8]; float pbk[8];
#pragma unroll
    for (int j = 0; j < 8; j++) {
        const int t = 1 + j;
        if (t < Tl) {
            pf[j]  = *(const float4*)(cmp + (size_t)t * CW + 4 * k);
            pbk[j] = cmp[(size_t)t * CW + 128];
        } else { pf[j] = make_float4(0.f,0.f,0.f,0.f); pbk[j] = 0.f; }
    }
    // p for the current step, computed one step ahead (ex2 off the chain).
    float qb = ex2f(pbk[0] * L2E_F);
    float q0 = ex2f(pf[0].x * L2E_F), q1 = ex2f(pf[0].y * L2E_F);
    float q2 = ex2f(pf[0].z * L2E_F), q3 = ex2f(pf[0].w * L2E_F);

    for (int t0 = 1; t0 < Tl; t0 += 8) {
#pragma unroll
        for (int j = 0; j < 8; j++) {
            const int t = t0 + j;
            if (t >= Tl) break;                          // Tl warp-uniform

            const float pb = qb, p0 = q0, p1 = q1, p2 = q2, p3 = q3;
            {
                const int jn = (j + 1) & 7;              // next step's emissions
                qb = ex2f(pbk[jn]  * L2E_F);
                q0 = ex2f(pf[jn].x * L2E_F); q1 = ex2f(pf[jn].y * L2E_F);
                q2 = ex2f(pf[jn].z * L2E_F); q3 = ex2f(pf[jn].w * L2E_F);
            }

            float nb7 = __shfl_up_sync(0xffffffffu, a7, 1);   // alpha[8k-1]
            nb7 = (k == 0) ? 0.f : nb7 * cross;               // rescale to my domain

            const float n0 = (a0 + nb7) * pb;                  // blank
            const float n1 = fmaf(c1, nb7, a1 + a0) * p0;      // label 4k
            const float n2 = (a2 + a1) * pb;
            const float n3 = fmaf(c3, a1, a3 + a2) * p1;
            const float n4 = (a4 + a3) * pb;
            const float n5 = fmaf(c5, a3, a5 + a4) * p2;
            const float n6 = (a6 + a5) * pb;
            const float n7 = fmaf(c7, a5, a7 + a6) * p3;
            const float n8 = (a8 + a7) * pb;                   // state 256 (lane 31)
            a0=n0; a1=n1; a2=n2; a3=n3; a4=n4; a5=n5; a6=n6; a7=n7; a8=n8;

            const int tn = t + 8;                              // refill slot j
            if (tn < Tl) {
                pf[j]  = *(const float4*)(cmp + (size_t)tn * CW + 4 * k);
                pbk[j] = cmp[(size_t)tn * CW + 128];
            } else { pf[j] = make_float4(0.f,0.f,0.f,0.f); pbk[j] = 0.f; }
        }

        // Per-lane renorm: bring lane-local max back to ~2^64; track in sacc.
        float m = fmaxf(fmaxf(fmaxf(a0,a1), fmaxf(a2,a3)),
                        fmaxf(fmaxf(a4,a5), fmaxf(a6,a7)));
        m = fmaxf(m, a8);
        const int nbs = __shfl_up_sync(0xffffffffu, sacc, 1);  // neighbor's old sacc
        if (m > 0.f) {
            const int e = (int)(__float_as_uint(m) >> 23) - 127;
            int s = 64 - e;
            s = max(-126, min(126, s));
            const float sc = pow2i(s);
            a0*=sc; a1*=sc; a2*=sc; a3*=sc; a4*=sc; a5*=sc; a6*=sc; a7*=sc; a8*=sc;
            sacc += s;
        } else if (k > 0) {
            sacc = nbs;           // empty lane: adopt neighbor's scale so the
        }                         // reachability wave arrives representable
        const int nbs2 = __shfl_up_sync(0xffffffffu, sacc, 1); // neighbor's new sacc
        int ds = sacc - nbs2;
        ds = max(-126, min(126, ds));
        cross = pow2i(ds);
    }

    // Readout: states + per-lane scales through shared memory; lane 0 combines.
    __shared__ float shv[Bc == 0 ? 1 : 257];   // per-CTA
    __shared__ int   shs[32];
    shv[8*k+0]=a0; shv[8*k+1]=a1; shv[8*k+2]=a2; shv[8*k+3]=a3;
    shv[8*k+4]=a4; shv[8*k+5]=a5; shv[8*k+6]=a6; shv[8*k+7]=a7;
    if (k == 31) shv[256] = a8;
    shs[k] = sacc;
    __syncwarp();
    if (k == 0) {
        const int tt = min(tl[b], Sc);
        const int i1 = 2 * tt;
        const int i2 = max(i1 - 1, 0);
        const float v1 = shv[i1], v2 = shv[i2];
        const int   s1 = shs[min(i1 >> 3, 31)];
        const int   s2 = shs[min(i2 >> 3, 31)];
        const float L1 = lg2f(v1) - (float)s1;   // log2 of true alpha
        const float L2 = lg2f(v2) - (float)s2;
        const float mm = fmaxf(L1, L2);
        const float ll2 = mm + lg2f(ex2f(L1 - mm) + ex2f(L2 - mm));
        atomicAdd(out, -ll2 * LN2_F);
    }
}

extern "C" void kernel_launch(void* const* d_in, const int* in_sizes, int n_in,
                              void* d_out, int out_size)
{
    const float* logp = (const float*)d_in[0];
    const int*   tg   = (const int*)d_in[1];
    const int*   il   = (const int*)d_in[2];
    const int*   tl   = (const int*)d_in[3];
    float*       out  = (float*)d_out;

    const int B = in_sizes[2];

    zero_k<<<(out_size + 255) / 256, 256>>>(out, out_size);

    dim3 ggrid((Tc + 3) / 4, B);
    gather_k<<<ggrid, 512>>>(logp, tg);

    ctc_dp<<<B, 32>>>(tg, il, tl, out);
}

// round 6
// speedup vs baseline: 1.6433x; 1.1627x over previous
#include <cuda_runtime.h>
#include <cuda_bf16.h>

// CTC forward loss, linear-probability domain with PER-LANE block floating
// point. log_probs [B=32,T=2000,V=1024] f32, targets [B,128] i32, lengths [B]
// i32 -> scalar f32 (sum of NLL).
//
//  1) gather_k : p = exp2(logp*log2e) for the 129 needed columns per (b,t),
//                compacted into g_compact[b,t,0..128]. Does the scattered
//                gather AND all transcendentals once at full-chip parallelism.
//                Block (0,0) also zeroes the output scalar.
//  2) ctc_dp   : one warp per batch; 257 lattice states in registers (8/lane,
//                lane 31 holds a 9th). Jacobi step, PURE fma-pipe:
//                a'[l] = (a[l]+a[l-1]+skip*a[l-2]) * p[l]; ONE shfl per step,
//                no MUFU, no smem, no barriers. Per-lane power-of-two scale
//                (renorm every 8 steps) gives unbounded global dynamic range;
//                the shfl'd neighbor value is rescaled by 2^(ds) per step.
//                Emissions prefetched 12 steps deep (window ~600 cy).

#define L2E_F 1.4426950408889634f
#define LN2_F 0.6931471805599453f

static constexpr int Bc = 32;
static constexpr int Tc = 2000;
static constexpr int Vc = 1024;
static constexpr int Sc = 128;
static constexpr int CW = 132;     // compact row stride in floats (16B multiple)
static constexpr int PD = 12;      // DP prefetch depth (timesteps)

__device__ float g_compact[(size_t)Bc * Tc * CW];

__device__ __forceinline__ float ex2f(float x) {
    float y; asm("ex2.approx.f32 %0, %1;" : "=f"(y) : "f"(x)); return y;
}
__device__ __forceinline__ float lg2f(float x) {
    float y; asm("lg2.approx.f32 %0, %1;" : "=f"(y) : "f"(x)); return y;
}
__device__ __forceinline__ float pow2i(int s) {      // s in [-126,127]
    return __uint_as_float((unsigned)(127 + s) << 23);
}

// grid ((Tc+3)/4, B), block 512: 4 time-rows per block, 128 label-threads each.
__global__ void gather_k(const float* __restrict__ logp, const int* __restrict__ tg,
                         float* __restrict__ out, int out_n)
{
    if (blockIdx.x == 0 && blockIdx.y == 0 && threadIdx.x == 0)
        for (int i = 0; i < out_n; i++) out[i] = 0.0f;

    const int b = blockIdx.y;
    const int j = threadIdx.x & 127;
    const int t = blockIdx.x * 4 + (threadIdx.x >> 7);
    if (t >= Tc) return;
    const size_t ri = ((size_t)b * Tc + t) * Vc;
    const size_t ro = ((size_t)b * Tc + t) * CW;
    const int lab = tg[b * Sc + j];
    g_compact[ro + j] = ex2f(logp[ri + lab] * L2E_F);
    if (j == 0) g_compact[ro + 128] = ex2f(logp[ri] * L2E_F);   // blank = vocab 0
}

__global__ __launch_bounds__(32, 1)
void ctc_dp(const int* __restrict__ tg, const int* __restrict__ il,
            const int* __restrict__ tl, float* __restrict__ out)
{
    const int b = blockIdx.x;
    const int k = threadIdx.x;                 // lane: states 8k..8k+7 (+256 on lane 31)
    const float* cmp = g_compact + (size_t)b * Tc * CW;

    // Skip-transition coefficients: label s vs s-1, s = 4k..4k+3.
    const int l0 = tg[b * Sc + 4 * k + 0];
    const int l1 = tg[b * Sc + 4 * k + 1];
    const int l2 = tg[b * Sc + 4 * k + 2];
    const int l3 = tg[b * Sc + 4 * k + 3];
    const int lm = (k == 0) ? -1 : tg[b * Sc + 4 * k - 1];
    const float c1 = (l0 != lm) ? 1.f : 0.f;   // lane 0: nb7 forced 0 anyway
    const float c3 = (l1 != l0) ? 1.f : 0.f;
    const float c5 = (l2 != l1) ? 1.f : 0.f;
    const float c7 = (l3 != l2) ? 1.f : 0.f;

    const int Tl = min(il[b], Tc);

    // States, stored = true * 2^sacc (per-lane scale). Init t=0 at 2^64.
    float a0=0.f,a1=0.f,a2=0.f,a3=0.f,a4=0.f,a5=0.f,a6=0.f,a7=0.f,a8=0.f;
    if (k == 0) {
        const float s64 = pow2i(64);
        a0 = cmp[128] * s64;                   // state 0: blank
        a1 = cmp[0]   * s64;                   // state 1: label s=0
    }
    int sacc = 64;
    float cross = 1.0f;                        // 2^(sacc_k - sacc_{k-1})

    // Emission prefetch ring, PD steps deep; slot j consumed PD steps after refill.
    float4 pf[PD]; float pbk[PD];
#pragma unroll
    for (int j = 0; j < PD; j++) {
        const int t = 1 + j;
        if (t < Tl) {
            pf[j]  = *(const float4*)(cmp + (size_t)t * CW + 4 * k);
            pbk[j] = cmp[(size_t)t * CW + 128];
        } else { pf[j] = make_float4(0.f,0.f,0.f,0.f); pbk[j] = 0.f; }
    }

    int rcount = 0;                            // steps since last renorm
    for (int t0 = 1; t0 < Tl; t0 += PD) {
#pragma unroll
        for (int j = 0; j < PD; j++) {
            const int t = t0 + j;
            if (t >= Tl) break;                          // Tl warp-uniform

            const float4 pv = pf[j];
            const float  pb = pbk[j];

            float nb7 = __shfl_up_sync(0xffffffffu, a7, 1);   // alpha[8k-1]
            nb7 = (k == 0) ? 0.f : nb7 * cross;               // rescale to my domain

            const float n0 = (a0 + nb7) * pb;                  // blank
            const float n1 = fmaf(c1, nb7, a1 + a0) * pv.x;    // label 4k
            const float n2 = (a2 + a1) * pb;
            const float n3 = fmaf(c3, a1, a3 + a2) * pv.y;
            const float n4 = (a4 + a3) * pb;
            const float n5 = fmaf(c5, a3, a5 + a4) * pv.z;
            const float n6 = (a6 + a5) * pb;
            const float n7 = fmaf(c7, a5, a7 + a6) * pv.w;
            const float n8 = (a8 + a7) * pb;                   // state 256 (lane 31)
            a0=n0; a1=n1; a2=n2; a3=n3; a4=n4; a5=n5; a6=n6; a7=n7; a8=n8;

            const int tn = t + PD;                             // refill slot j
            if (tn < Tl) {
                pf[j]  = *(const float4*)(cmp + (size_t)tn * CW + 4 * k);
                pbk[j] = cmp[(size_t)tn * CW + 128];
            } else { pf[j] = make_float4(0.f,0.f,0.f,0.f); pbk[j] = 0.f; }

            // Per-lane renorm every 8 steps (keeps 8-step emission drop ~2^-90
            // inside the fp32 window from a 2^64-normalized lane max).
            if (++rcount == 8) {
                rcount = 0;
                float m = fmaxf(fmaxf(fmaxf(a0,a1), fmaxf(a2,a3)),
                                fmaxf(fmaxf(a4,a5), fmaxf(a6,a7)));
                m = fmaxf(m, a8);
                const int nbs = __shfl_up_sync(0xffffffffu, sacc, 1);
                if (m > 0.f) {
                    const int e = (int)(__float_as_uint(m) >> 23) - 127;
                    int s = 64 - e;
                    s = max(-126, min(126, s));
                    const float sc = pow2i(s);
                    a0*=sc; a1*=sc; a2*=sc; a3*=sc; a4*=sc;
                    a5*=sc; a6*=sc; a7*=sc; a8*=sc;
                    sacc += s;
                } else if (k > 0) {
                    sacc = nbs;        // empty lane adopts neighbor's scale
                }
                const int nbs2 = __shfl_up_sync(0xffffffffu, sacc, 1);
                int ds = sacc - nbs2;
                ds = max(-126, min(126, ds));
                cross = pow2i(ds);
            }
        }
    }

    // Readout: states + per-lane scales through shared memory; lane 0 combines.
    __shared__ float shv[257];
    __shared__ int   shs[32];
    shv[8*k+0]=a0; shv[8*k+1]=a1; shv[8*k+2]=a2; shv[8*k+3]=a3;
    shv[8*k+4]=a4; shv[8*k+5]=a5; shv[8*k+6]=a6; shv[8*k+7]=a7;
    if (k == 31) shv[256] = a8;
    shs[k] = sacc;
    __syncwarp();
    if (k == 0) {
        const int tt = min(tl[b], Sc);
        const int i1 = 2 * tt;
        const int i2 = max(i1 - 1, 0);
        const float v1 = shv[i1], v2 = shv[i2];
        const int   s1 = shs[min(i1 >> 3, 31)];
        const int   s2 = shs[min(i2 >> 3, 31)];
        const float L1 = lg2f(v1) - (float)s1;     // log2 of true alpha
        const float L2 = lg2f(v2) - (float)s2;
        const float mm = fmaxf(L1, L2);
        const float ll2 = mm + lg2f(ex2f(L1 - mm) + ex2f(L2 - mm));
        atomicAdd(out, -ll2 * LN2_F);
    }
}

extern "C" void kernel_launch(void* const* d_in, const int* in_sizes, int n_in,
                              void* d_out, int out_size)
{
    const float* logp = (const float*)d_in[0];
    const int*   tg   = (const int*)d_in[1];
    const int*   il   = (const int*)d_in[2];
    const int*   tl   = (const int*)d_in[3];
    float*       out  = (float*)d_out;

    const int B = in_sizes[2];

    dim3 ggrid((Tc + 3) / 4, B);
    gather_k<<<ggrid, 512>>>(logp, tg, out, out_size);

    ctc_dp<<<B, 32>>>(tg, il, tl, out);
}

// round 7
// speedup vs baseline: 1.8399x; 1.1196x over previous
#include <cuda_runtime.h>
#include <cuda_bf16.h>

// CTC forward loss, linear-probability domain with PER-LANE block floating
// point. log_probs [B=32,T=2000,V=1024] f32, targets [B,128] i32, lengths [B]
// i32 -> scalar f32 (sum of NLL).
//
//  1) gather_k : p = exp2(logp*log2e) for the 129 needed columns per (b,t),
//                compacted into g_compact[b, t, 0..128] (padded to Tc+8 rows
//                per batch so the DP prefetch never needs a bounds check).
//                Block (0,0) also zeroes the output scalar.
//  2) ctc_dp   : one warp per batch; 257 lattice states in registers (8/lane,
//                lane 31 holds a 9th). Jacobi step, pure fma-pipe:
//                a'[l] = (a[l]+a[l-1]+skip*a[l-2]) * p[l]; ONE shfl per step.
//                MAIN LOOP IS BRANCH-FREE: 8 straight-line steps per block
//                (no per-step exit test, unconditional refills into the padded
//                buffer, renorm hoisted to block end) so ptxas can pipeline
//                across steps. Per-lane power-of-two scale (renorm to 2^64
//                every 8 steps) gives unbounded global dynamic range.

#define L2E_F 1.4426950408889634f
#define LN2_F 0.6931471805599453f

static constexpr int Bc = 32;
static constexpr int Tc = 2000;
static constexpr int Vc = 1024;
static constexpr int Sc = 128;
static constexpr int CW = 132;       // compact row stride in floats (16B multiple)
static constexpr int PD = 8;         // prefetch depth == block length
static constexpr int TP = Tc + PD;   // padded rows per batch

__device__ float g_compact[(size_t)Bc * TP * CW];

__device__ __forceinline__ float ex2f(float x) {
    float y; asm("ex2.approx.f32 %0, %1;" : "=f"(y) : "f"(x)); return y;
}
__device__ __forceinline__ float lg2f(float x) {
    float y; asm("lg2.approx.f32 %0, %1;" : "=f"(y) : "f"(x)); return y;
}
__device__ __forceinline__ float pow2i(int s) {      // s in [-126,127]
    return __uint_as_float((unsigned)(127 + s) << 23);
}

// grid ((Tc+3)/4, B), block 512: 4 time-rows per block, 128 label-threads each.
__global__ void gather_k(const float* __restrict__ logp, const int* __restrict__ tg,
                         float* __restrict__ out, int out_n)
{
    if (blockIdx.x == 0 && blockIdx.y == 0 && threadIdx.x == 0)
        for (int i = 0; i < out_n; i++) out[i] = 0.0f;

    const int b = blockIdx.y;
    const int j = threadIdx.x & 127;
    const int t = blockIdx.x * 4 + (threadIdx.x >> 7);
    if (t >= Tc) return;
    const size_t ri = ((size_t)b * Tc + t) * Vc;
    const size_t ro = ((size_t)b * TP + t) * CW;
    const int lab = tg[b * Sc + j];
    g_compact[ro + j] = ex2f(logp[ri + lab] * L2E_F);
    if (j == 0) g_compact[ro + 128] = ex2f(logp[ri] * L2E_F);   // blank = vocab 0
}

__global__ __launch_bounds__(32, 1)
void ctc_dp(const int* __restrict__ tg, const int* __restrict__ il,
            const int* __restrict__ tl, float* __restrict__ out)
{
    const int b = blockIdx.x;
    const int k = threadIdx.x;                 // lane: states 8k..8k+7 (+256 on lane 31)
    const float* cmp = g_compact + (size_t)b * TP * CW;

    // Skip-transition coefficients: label s vs s-1, s = 4k..4k+3.
    const int l0 = tg[b * Sc + 4 * k + 0];
    const int l1 = tg[b * Sc + 4 * k + 1];
    const int l2 = tg[b * Sc + 4 * k + 2];
    const int l3 = tg[b * Sc + 4 * k + 3];
    const int lm = (k == 0) ? -1 : tg[b * Sc + 4 * k - 1];
    const float c1 = (l0 != lm) ? 1.f : 0.f;   // lane 0: nb7 forced 0 via cross
    const float c3 = (l1 != l0) ? 1.f : 0.f;
    const float c5 = (l2 != l1) ? 1.f : 0.f;
    const float c7 = (l3 != l2) ? 1.f : 0.f;

    const int Tl = min(il[b], Tc);

    // States, stored = true * 2^sacc (per-lane scale). Init t=0 at 2^64.
    float a0=0.f,a1=0.f,a2=0.f,a3=0.f,a4=0.f,a5=0.f,a6=0.f,a7=0.f,a8=0.f;
    if (k == 0) {
        const float s64 = pow2i(64);
        a0 = cmp[128] * s64;                   // state 0: blank
        a1 = cmp[0]   * s64;                   // state 1: label s=0
    }
    int sacc = 64;
    float cross = (k == 0) ? 0.f : 1.0f;       // 2^(sacc_k - sacc_{k-1}); 0 kills
                                               // the nonexistent left neighbor

    // Emission prefetch ring: slot j holds row t0+j at the top of each block.
    // Padded buffer => priming and refills are unconditional.
    float4 pf[PD]; float pbk[PD];
#pragma unroll
    for (int j = 0; j < PD; j++) {
        pf[j]  = *(const float4*)(cmp + (size_t)(1 + j) * CW + 4 * k);
        pbk[j] = cmp[(size_t)(1 + j) * CW + 128];
    }

    int t0 = 1;
    for (; t0 + PD <= Tl; t0 += PD) {
#pragma unroll
        for (int j = 0; j < PD; j++) {         // 8 straight-line steps, no branches
            const float4 pv = pf[j];
            const float  pb = pbk[j];

            const float nb7 = __shfl_up_sync(0xffffffffu, a7, 1) * cross;

            const float n0 = (a0 + nb7) * pb;                  // blank
            const float n1 = fmaf(c1, nb7, a1 + a0) * pv.x;    // label 4k
            const float n2 = (a2 + a1) * pb;
            const float n3 = fmaf(c3, a1, a3 + a2) * pv.y;
            const float n4 = (a4 + a3) * pb;
            const float n5 = fmaf(c5, a3, a5 + a4) * pv.z;
            const float n6 = (a6 + a5) * pb;
            const float n7 = fmaf(c7, a5, a7 + a6) * pv.w;
            const float n8 = (a8 + a7) * pb;                   // state 256 (lane 31)
            a0=n0; a1=n1; a2=n2; a3=n3; a4=n4; a5=n5; a6=n6; a7=n7; a8=n8;

            const size_t rn = (size_t)(t0 + j + PD) * CW;      // unconditional refill
            pf[j]  = *(const float4*)(cmp + rn + 4 * k);
            pbk[j] = cmp[rn + 128];
        }

        // Per-lane renorm once per block: lane max back to 2^64, scale in sacc.
        float m = fmaxf(fmaxf(fmaxf(a0,a1), fmaxf(a2,a3)),
                        fmaxf(fmaxf(a4,a5), fmaxf(a6,a7)));
        m = fmaxf(m, a8);
        const int nbs = __shfl_up_sync(0xffffffffu, sacc, 1);
        if (m > 0.f) {
            const int e = (int)(__float_as_uint(m) >> 23) - 127;
            int s = 64 - e;
            s = max(-126, min(126, s));
            const float sc = pow2i(s);
            a0*=sc; a1*=sc; a2*=sc; a3*=sc; a4*=sc;
            a5*=sc; a6*=sc; a7*=sc; a8*=sc;
            sacc += s;
        } else if (k > 0) {
            sacc = nbs;                        // empty lane adopts neighbor's scale
        }
        const int nbs2 = __shfl_up_sync(0xffffffffu, sacc, 1);
        int ds = sacc - nbs2;
        ds = max(-126, min(126, ds));
        cross = (k == 0) ? 0.f : pow2i(ds);
    }

    // Tail block (< PD steps), guarded; static pf indexing keeps ring in regs.
#pragma unroll
    for (int j = 0; j < PD; j++) {
        if (t0 + j >= Tl) break;
        const float4 pv = pf[j];
        const float  pb = pbk[j];

        const float nb7 = __shfl_up_sync(0xffffffffu, a7, 1) * cross;

        const float n0 = (a0 + nb7) * pb;
        const float n1 = fmaf(c1, nb7, a1 + a0) * pv.x;
        const float n2 = (a2 + a1) * pb;
        const float n3 = fmaf(c3, a1, a3 + a2) * pv.y;
        const float n4 = (a4 + a3) * pb;
        const float n5 = fmaf(c5, a3, a5 + a4) * pv.z;
        const float n6 = (a6 + a5) * pb;
        const float n7 = fmaf(c7, a5, a7 + a6) * pv.w;
        const float n8 = (a8 + a7) * pb;
        a0=n0; a1=n1; a2=n2; a3=n3; a4=n4; a5=n5; a6=n6; a7=n7; a8=n8;
    }

    // Readout: states + per-lane scales through shared memory; lane 0 combines.
    __shared__ float shv[257];
    __shared__ int   shs[32];
    shv[8*k+0]=a0; shv[8*k+1]=a1; shv[8*k+2]=a2; shv[8*k+3]=a3;
    shv[8*k+4]=a4; shv[8*k+5]=a5; shv[8*k+6]=a6; shv[8*k+7]=a7;
    if (k == 31) shv[256] = a8;
    shs[k] = sacc;
    __syncwarp();
    if (k == 0) {
        const int tt = min(tl[b], Sc);
        const int i1 = 2 * tt;
        const int i2 = max(i1 - 1, 0);
        const float v1 = shv[i1], v2 = shv[i2];
        const int   s1 = shs[min(i1 >> 3, 31)];
        const int   s2 = shs[min(i2 >> 3, 31)];
        const float L1 = lg2f(v1) - (float)s1;     // log2 of true alpha
        const float L2 = lg2f(v2) - (float)s2;
        const float mm = fmaxf(L1, L2);
        const float ll2 = mm + lg2f(ex2f(L1 - mm) + ex2f(L2 - mm));
        atomicAdd(out, -ll2 * LN2_F);
    }
}

extern "C" void kernel_launch(void* const* d_in, const int* in_sizes, int n_in,
                              void* d_out, int out_size)
{
    const float* logp = (const float*)d_in[0];
    const int*   tg   = (const int*)d_in[1];
    const int*   il   = (const int*)d_in[2];
    const int*   tl   = (const int*)d_in[3];
    float*       out  = (float*)d_out;

    const int B = in_sizes[2];

    dim3 ggrid((Tc + 3) / 4, B);
    gather_k<<<ggrid, 512>>>(logp, tg, out, out_size);

    ctc_dp<<<B, 32>>>(tg, il, tl, out);
}